// round 10
// baseline (speedup 1.0000x reference)
#include <cuda_runtime.h>
#include <math.h>

#define HW    4096
#define CFULL 256
#define C4    64
#define BATCH 4

typedef unsigned long long u64;

// Scratch: projections. Slots p=0,1,2 (q, kl, kf) stored TRANSPOSED [hw][64];
// slot p=3 (v) stored natural [64][hw]. Each slot is 64*4096 floats.
__device__ float g_proj[(size_t)16 * C4 * HW];          // 16 MB
__device__ float g_fused[(size_t)BATCH * 128 * HW];     // 8 MB

// ---------------- packed f32x2 helpers (sm_103a FFMA2 path) ----------------
__device__ __forceinline__ u64 pack2(float x, float y) {
    u64 r; asm("mov.b64 %0, {%1, %2};" : "=l"(r) : "f"(x), "f"(y)); return r;
}
__device__ __forceinline__ u64 dup2(float x) {
    u64 r; asm("mov.b64 %0, {%1, %1};" : "=l"(r) : "f"(x)); return r;
}
__device__ __forceinline__ float2 unpk(u64 v) {
    float2 f; asm("mov.b64 {%0, %1}, %2;" : "=f"(f.x), "=f"(f.y) : "l"(v)); return f;
}
__device__ __forceinline__ void fma2(u64& d, u64 a, u64 b) {
    asm("fma.rn.f32x2 %0, %1, %2, %0;" : "+l"(d) : "l"(a), "l"(b));
}
__device__ __forceinline__ void mul2(u64& d, u64 a) {
    asm("mul.rn.f32x2 %0, %0, %1;" : "+l"(d) : "l"(a));
}

// ---------------------------------------------------------------------------
// Kernel 1: fused 1x1-conv projections with FFMA2.
// p: 0=q(cur,Wqk) 1=kl(last,Wkl) 2=kf(fut,Wkf) 3=v(cur,Wv)
// p<3 -> transposed output [hw][64]; p==3 -> natural [64][hw].
// Tiles: 64 o x 128 hw, BK=32. 256 threads (16tx x 16ty), 4o x 8hw per thread.
// ---------------------------------------------------------------------------
__global__ __launch_bounds__(256) void proj_kernel(
    const float* __restrict__ last, const float* __restrict__ cur, const float* __restrict__ fut,
    const float* __restrict__ Wqk, const float* __restrict__ bqk,
    const float* __restrict__ Wkl, const float* __restrict__ bkl,
    const float* __restrict__ Wkf, const float* __restrict__ bkf,
    const float* __restrict__ Wv,  const float* __restrict__ bv)
{
    __shared__ __align__(16) float sbuf[128 * 66];   // 33792 B; reused as Ts
    float* Ws = sbuf;                 // 32 x 68 (pad)
    float* Xs = sbuf + 32 * 68;       // 32 x 128
    float* Ts = sbuf;                 // 128 x 66 transpose staging

    int p = blockIdx.y, b = blockIdx.z;
    const float* X; const float* W; const float* bias;
    if (p == 0)      { X = cur;  W = Wqk; bias = bqk; }
    else if (p == 1) { X = last; W = Wkl; bias = bkl; }
    else if (p == 2) { X = fut;  W = Wkf; bias = bkf; }
    else             { X = cur;  W = Wv;  bias = bv;  }
    X += (size_t)b * CFULL * HW;

    int hw0 = blockIdx.x * 128;
    int tid = threadIdx.x;
    int tx = tid & 15, ty = tid >> 4;

    u64 acc2[4][4];
#pragma unroll
    for (int i = 0; i < 4; i++)
#pragma unroll
        for (int j = 0; j < 4; j++) acc2[i][j] = 0ull;

    for (int c0 = 0; c0 < CFULL; c0 += 32) {
        __syncthreads();
#pragma unroll
        for (int i = 0; i < 8; i++) {           // 64o x 32k W tile
            int idx = tid + i * 256;
            int k = idx & 31, o = idx >> 5;
            Ws[k * 68 + o] = W[o * CFULL + c0 + k];
        }
#pragma unroll
        for (int i = 0; i < 4; i++) {           // 32k x 128 X tile, float4
            int ch = tid + i * 256;
            int k = ch >> 5, j4 = ch & 31;
            *(float4*)&Xs[k * 128 + j4 * 4] =
                *(const float4*)&X[(size_t)(c0 + k) * HW + hw0 + j4 * 4];
        }
        __syncthreads();
#pragma unroll
        for (int k = 0; k < 32; k++) {
            float4 a4 = *(const float4*)&Ws[k * 68 + ty * 4];
            u64 ad[4] = {dup2(a4.x), dup2(a4.y), dup2(a4.z), dup2(a4.w)};
            ulonglong2 b0 = *(const ulonglong2*)&Xs[k * 128 + tx * 8];
            ulonglong2 b1 = *(const ulonglong2*)&Xs[k * 128 + tx * 8 + 4];
            u64 bb[4] = {b0.x, b0.y, b1.x, b1.y};
#pragma unroll
            for (int i = 0; i < 4; i++)
#pragma unroll
                for (int j = 0; j < 4; j++) fma2(acc2[i][j], ad[i], bb[j]);
        }
    }

    // unpack + bias
    float v[4][8];
#pragma unroll
    for (int i = 0; i < 4; i++) {
        float bo = bias[ty * 4 + i];
#pragma unroll
        for (int j = 0; j < 4; j++) {
            float2 t = unpk(acc2[i][j]);
            v[i][2 * j]     = t.x + bo;
            v[i][2 * j + 1] = t.y + bo;
        }
    }

    float* out = g_proj + (size_t)(p * 4 + b) * C4 * HW;
    if (p == 3) {
        // natural [o][hw]
#pragma unroll
        for (int i = 0; i < 4; i++) {
            int o = ty * 4 + i;
            *(float4*)&out[(size_t)o * HW + hw0 + tx * 8] =
                make_float4(v[i][0], v[i][1], v[i][2], v[i][3]);
            *(float4*)&out[(size_t)o * HW + hw0 + tx * 8 + 4] =
                make_float4(v[i][4], v[i][5], v[i][6], v[i][7]);
        }
    } else {
        // transposed [hw][o] via smem staging
        __syncthreads();   // everyone done reading Ws/Xs before aliasing Ts
#pragma unroll
        for (int j = 0; j < 8; j++) {
            int hw = tx * 8 + j;
            *(u64*)&Ts[hw * 66 + ty * 4]     = pack2(v[0][j], v[1][j]);
            *(u64*)&Ts[hw * 66 + ty * 4 + 2] = pack2(v[2][j], v[3][j]);
        }
        __syncthreads();
#pragma unroll
        for (int i2 = 0; i2 < 16; i2++) {
            int ch = tid + i2 * 256;        // float2 chunks: 128 rows x 32
            int r = ch >> 5, c2 = ch & 31;
            *(float2*)&out[(size_t)(hw0 + r) * C4 + 2 * c2] =
                *(const float2*)&Ts[r * 66 + 2 * c2];
        }
    }
}

// ---------------------------------------------------------------------------
// Kernel 2: flash attention, FFMA2 inner-product form.
// Bq=Bk=64, 128 threads (16ty x 8tx), 4q x 8(k|c) per thread.
// Tiles row-major with contraction contiguous, pad 66:
//   Qs[q][d], Ks[k][d], Vs[c][k], Ps[q][k]  (each 64 x 66)
// ---------------------------------------------------------------------------
__global__ __launch_bounds__(128) void attn_kernel()
{
    extern __shared__ __align__(16) float sm[];
    float* Qs = sm;                  // 64*66
    float* Ks = sm + 64 * 66;
    float* Vs = sm + 2 * 64 * 66;
    float* Ps = sm + 3 * 64 * 66;

    int tid = threadIdx.x;
    int tx = tid & 7, ty = tid >> 3;      // tx: 8-wide (k/c), ty: 16 (q)
    int b = blockIdx.z, a = blockIdx.y;
    int q0 = blockIdx.x * 64;

    const float* qT = g_proj + (size_t)(0 * 4 + b) * C4 * HW;        // [hw][64]
    const float* kT = g_proj + (size_t)((1 + a) * 4 + b) * C4 * HW;  // [hw][64]
    const float* vb = g_proj + (size_t)(3 * 4 + b) * C4 * HW;        // [64][hw]

    // load Q tile rows [q][d]
#pragma unroll
    for (int i = 0; i < 8; i++) {
        int ch = tid + i * 128;           // float4 chunks 0..1023
        int r = ch >> 4, cc = ch & 15;
        float4 v4 = *(const float4*)&qT[(size_t)(q0 + r) * C4 + cc * 4];
        *(float2*)&Qs[r * 66 + cc * 4]     = make_float2(v4.x, v4.y);
        *(float2*)&Qs[r * 66 + cc * 4 + 2] = make_float2(v4.z, v4.w);
    }

    u64 acc2[4][8];
    float m[4], l[4];
#pragma unroll
    for (int i = 0; i < 4; i++) {
        m[i] = -1e30f; l[i] = 0.f;
#pragma unroll
        for (int j = 0; j < 8; j++) acc2[i][j] = 0ull;
    }

    const float* Qrow = Qs + (ty * 4) * 66;
    const float* Krow = Ks + (tx * 8) * 66;
    const float* Vrow = Vs + (tx * 8) * 66;
    const float* Prow = Ps + (ty * 4) * 66;

    for (int kt = 0; kt < 64; kt++) {
        int k0 = kt * 64;
        __syncthreads();   // prev GEMM2 done with Ps/Vs; GEMM1 done with Ks
#pragma unroll
        for (int i = 0; i < 8; i++) {
            int ch = tid + i * 128;
            int r = ch >> 4, cc = ch & 15;
            float4 kv = *(const float4*)&kT[(size_t)(k0 + r) * C4 + cc * 4];
            *(float2*)&Ks[r * 66 + cc * 4]     = make_float2(kv.x, kv.y);
            *(float2*)&Ks[r * 66 + cc * 4 + 2] = make_float2(kv.z, kv.w);
            float4 vv = *(const float4*)&vb[(size_t)r * HW + k0 + cc * 4];
            *(float2*)&Vs[r * 66 + cc * 4]     = make_float2(vv.x, vv.y);
            *(float2*)&Vs[r * 66 + cc * 4 + 2] = make_float2(vv.z, vv.w);
        }
        __syncthreads();

        // GEMM1: s[q,k] = sum_d Q[q,d]*K[k,d], pairwise-packed along d
        u64 s2[4][8];
#pragma unroll
        for (int i = 0; i < 4; i++)
#pragma unroll
            for (int j = 0; j < 8; j++) s2[i][j] = 0ull;
#pragma unroll 8
        for (int dd = 0; dd < 32; dd++) {
            u64 av[4], bv2[8];
#pragma unroll
            for (int i = 0; i < 4; i++) av[i] = *(const u64*)(Qrow + i * 66 + 2 * dd);
#pragma unroll
            for (int j = 0; j < 8; j++) bv2[j] = *(const u64*)(Krow + j * 66 + 2 * dd);
#pragma unroll
            for (int i = 0; i < 4; i++)
#pragma unroll
                for (int j = 0; j < 8; j++) fma2(s2[i][j], av[i], bv2[j]);
        }

        // online softmax over key axis (reduce across 8 tx lanes)
#pragma unroll
        for (int i = 0; i < 4; i++) {
            float e[8];
            float rm = -1e30f;
#pragma unroll
            for (int j = 0; j < 8; j++) {
                float2 t = unpk(s2[i][j]);
                e[j] = t.x + t.y;
                rm = fmaxf(rm, e[j]);
            }
            rm = fmaxf(rm, __shfl_xor_sync(0xffffffffu, rm, 1));
            rm = fmaxf(rm, __shfl_xor_sync(0xffffffffu, rm, 2));
            rm = fmaxf(rm, __shfl_xor_sync(0xffffffffu, rm, 4));
            float mn = fmaxf(m[i], rm);
            float sc = __expf(m[i] - mn);
            m[i] = mn;
            float ps = 0.f;
#pragma unroll
            for (int j = 0; j < 8; j++) { e[j] = __expf(e[j] - mn); ps += e[j]; }
            ps += __shfl_xor_sync(0xffffffffu, ps, 1);
            ps += __shfl_xor_sync(0xffffffffu, ps, 2);
            ps += __shfl_xor_sync(0xffffffffu, ps, 4);
            l[i] = l[i] * sc + ps;
            u64 sc2 = dup2(sc);
#pragma unroll
            for (int j = 0; j < 8; j++) mul2(acc2[i][j], sc2);
            // store P row-major [q][k]
#pragma unroll
            for (int jp = 0; jp < 4; jp++)
                *(u64*)&Ps[(ty * 4 + i) * 66 + tx * 8 + 2 * jp] = pack2(e[2 * jp], e[2 * jp + 1]);
        }
        __syncthreads();

        // GEMM2: O[q,c] += sum_k P[q,k]*V[c,k], pairwise-packed along k
#pragma unroll 8
        for (int kk = 0; kk < 32; kk++) {
            u64 av[4], bv2[8];
#pragma unroll
            for (int i = 0; i < 4; i++) av[i] = *(const u64*)(Prow + i * 66 + 2 * kk);
#pragma unroll
            for (int j = 0; j < 8; j++) bv2[j] = *(const u64*)(Vrow + j * 66 + 2 * kk);
#pragma unroll
            for (int i = 0; i < 4; i++)
#pragma unroll
                for (int j = 0; j < 8; j++) fma2(acc2[i][j], av[i], bv2[j]);
        }
    }

    // epilogue: horizontal pair-sum, normalize, write fused[b, a*64+c, q]
    float* fo = g_fused + (size_t)b * 128 * HW + (size_t)a * 64 * HW;
    float val[4][8];
#pragma unroll
    for (int i = 0; i < 4; i++) {
        float inv = 1.f / l[i];
#pragma unroll
        for (int j = 0; j < 8; j++) {
            float2 t = unpk(acc2[i][j]);
            val[i][j] = (t.x + t.y) * inv;
        }
    }
#pragma unroll
    for (int j = 0; j < 8; j++) {
        *(float4*)&fo[(size_t)(tx * 8 + j) * HW + q0 + ty * 4] =
            make_float4(val[0][j], val[1][j], val[2][j], val[3][j]);
    }
}

// ---------------------------------------------------------------------------
// Kernel 3: fire conv (128->256) + BN + residual + ReLU, FFMA2.
// ---------------------------------------------------------------------------
__global__ __launch_bounds__(256) void fire_kernel(
    const float* __restrict__ Wfire, const float* __restrict__ bfire,
    const float* __restrict__ gamma, const float* __restrict__ beta,
    const float* __restrict__ mean,  const float* __restrict__ var,
    const float* __restrict__ cur, float* __restrict__ out)
{
    __shared__ __align__(16) float sbuf[32 * 68 + 32 * 128];
    float* Ws = sbuf;
    float* Xs = sbuf + 32 * 68;

    int b = blockIdx.z;
    int o0 = blockIdx.y * 64;
    int hw0 = blockIdx.x * 128;
    const float* X = g_fused + (size_t)b * 128 * HW;
    int tid = threadIdx.x, tx = tid & 15, ty = tid >> 4;

    u64 acc2[4][4];
#pragma unroll
    for (int i = 0; i < 4; i++)
#pragma unroll
        for (int j = 0; j < 4; j++) acc2[i][j] = 0ull;

    for (int c0 = 0; c0 < 128; c0 += 32) {
        __syncthreads();
#pragma unroll
        for (int i = 0; i < 8; i++) {
            int idx = tid + i * 256;
            int k = idx & 31, o = idx >> 5;
            Ws[k * 68 + o] = Wfire[(size_t)(o0 + o) * 128 + c0 + k];
        }
#pragma unroll
        for (int i = 0; i < 4; i++) {
            int ch = tid + i * 256;
            int k = ch >> 5, j4 = ch & 31;
            *(float4*)&Xs[k * 128 + j4 * 4] =
                *(const float4*)&X[(size_t)(c0 + k) * HW + hw0 + j4 * 4];
        }
        __syncthreads();
#pragma unroll
        for (int k = 0; k < 32; k++) {
            float4 a4 = *(const float4*)&Ws[k * 68 + ty * 4];
            u64 ad[4] = {dup2(a4.x), dup2(a4.y), dup2(a4.z), dup2(a4.w)};
            ulonglong2 b0 = *(const ulonglong2*)&Xs[k * 128 + tx * 8];
            ulonglong2 b1 = *(const ulonglong2*)&Xs[k * 128 + tx * 8 + 4];
            u64 bb[4] = {b0.x, b0.y, b1.x, b1.y};
#pragma unroll
            for (int i = 0; i < 4; i++)
#pragma unroll
                for (int j = 0; j < 4; j++) fma2(acc2[i][j], ad[i], bb[j]);
        }
    }

#pragma unroll
    for (int i = 0; i < 4; i++) {
        int o = o0 + ty * 4 + i;
        float inv = gamma[o] * rsqrtf(var[o] + 1e-5f);
        float sh  = beta[o] - mean[o] * inv;
        float bo  = bfire[o];
        float v[8];
#pragma unroll
        for (int j = 0; j < 4; j++) {
            float2 t = unpk(acc2[i][j]);
            v[2 * j]     = t.x;
            v[2 * j + 1] = t.y;
        }
#pragma unroll
        for (int j = 0; j < 8; j++) {
            size_t idx = ((size_t)b * CFULL + o) * HW + hw0 + tx * 8 + j;
            float fired = (v[j] + bo) * inv + sh;
            out[idx] = fmaxf(cur[idx] + fired, 0.f);
        }
    }
}

// ---------------------------------------------------------------------------
extern "C" void kernel_launch(void* const* d_in, const int* in_sizes, int n_in,
                              void* d_out, int out_size)
{
    const float* last  = (const float*)d_in[0];
    const float* cur   = (const float*)d_in[1];
    const float* fut   = (const float*)d_in[2];
    const float* Wqk   = (const float*)d_in[3];
    const float* bqk   = (const float*)d_in[4];
    const float* Wkl   = (const float*)d_in[5];
    const float* bkl   = (const float*)d_in[6];
    const float* Wkf   = (const float*)d_in[7];
    const float* bkf   = (const float*)d_in[8];
    const float* Wv    = (const float*)d_in[9];
    const float* bv    = (const float*)d_in[10];
    const float* Wfire = (const float*)d_in[11];
    const float* bfire = (const float*)d_in[12];
    const float* gamma = (const float*)d_in[13];
    const float* beta  = (const float*)d_in[14];
    const float* mean  = (const float*)d_in[15];
    const float* var   = (const float*)d_in[16];
    float* out = (float*)d_out;

    dim3 gA(HW / 128, 4, BATCH);
    proj_kernel<<<gA, 256>>>(last, cur, fut, Wqk, bqk, Wkl, bkl, Wkf, bkf, Wv, bv);

    size_t smB = (size_t)(4 * 64 * 66) * sizeof(float);   // 67584 B
    cudaFuncSetAttribute(attn_kernel, cudaFuncAttributeMaxDynamicSharedMemorySize, (int)smB);
    dim3 gB(HW / 64, 2, BATCH);
    attn_kernel<<<gB, 128, smB>>>();

    dim3 gC(HW / 128, CFULL / 64, BATCH);
    fire_kernel<<<gC, 256>>>(Wfire, bfire, gamma, beta, mean, var, cur, out);
}

// round 11
// speedup vs baseline: 1.7395x; 1.7395x over previous
#include <cuda_runtime.h>
#include <math.h>

#define HW    4096
#define CFULL 256
#define C4    64
#define BATCH 4

typedef unsigned long long u64;

// Scratch: projections. q(p=0), kl(p=1), kf(p=2) stored natural [64][HW];
// v (p=3) stored TRANSPOSED [HW][64]. Each slot is 64*4096 floats.
__device__ float g_proj[(size_t)16 * C4 * HW];          // 16 MB
__device__ float g_fused[(size_t)BATCH * 128 * HW];     // 8 MB

// ---------------- packed f32x2 helpers (sm_103a FFMA2 path) ----------------
__device__ __forceinline__ u64 pack2(float x, float y) {
    u64 r; asm("mov.b64 %0, {%1, %2};" : "=l"(r) : "f"(x), "f"(y)); return r;
}
__device__ __forceinline__ u64 dup2(float x) {
    u64 r; asm("mov.b64 %0, {%1, %1};" : "=l"(r) : "f"(x)); return r;
}
__device__ __forceinline__ float2 unpk(u64 v) {
    float2 f; asm("mov.b64 {%0, %1}, %2;" : "=f"(f.x), "=f"(f.y) : "l"(v)); return f;
}
__device__ __forceinline__ void fma2(u64& d, u64 a, u64 b) {
    asm("fma.rn.f32x2 %0, %1, %2, %0;" : "+l"(d) : "l"(a), "l"(b));
}
__device__ __forceinline__ void mul2(u64& d, u64 a) {
    asm("mul.rn.f32x2 %0, %0, %1;" : "+l"(d) : "l"(a));
}

// ---------------------------------------------------------------------------
// Kernel 1: fused 1x1-conv projections with FFMA2 (outer product).
// p: 0=q(cur,Wqk) 1=kl(last,Wkl) 2=kf(fut,Wkf) 3=v(cur,Wv)
// p<3 -> natural [o][hw]; p==3 -> transposed [hw][o].
// ---------------------------------------------------------------------------
__global__ __launch_bounds__(256) void proj_kernel(
    const float* __restrict__ last, const float* __restrict__ cur, const float* __restrict__ fut,
    const float* __restrict__ Wqk, const float* __restrict__ bqk,
    const float* __restrict__ Wkl, const float* __restrict__ bkl,
    const float* __restrict__ Wkf, const float* __restrict__ bkf,
    const float* __restrict__ Wv,  const float* __restrict__ bv)
{
    __shared__ __align__(16) float sbuf[128 * 66];   // reused as Ts for transpose
    float* Ws = sbuf;                 // 32 x 68 (pad)
    float* Xs = sbuf + 32 * 68;       // 32 x 128
    float* Ts = sbuf;                 // 128 x 66 transpose staging

    int p = blockIdx.y, b = blockIdx.z;
    const float* X; const float* W; const float* bias;
    if (p == 0)      { X = cur;  W = Wqk; bias = bqk; }
    else if (p == 1) { X = last; W = Wkl; bias = bkl; }
    else if (p == 2) { X = fut;  W = Wkf; bias = bkf; }
    else             { X = cur;  W = Wv;  bias = bv;  }
    X += (size_t)b * CFULL * HW;

    int hw0 = blockIdx.x * 128;
    int tid = threadIdx.x;
    int tx = tid & 15, ty = tid >> 4;

    u64 acc2[4][4];
#pragma unroll
    for (int i = 0; i < 4; i++)
#pragma unroll
        for (int j = 0; j < 4; j++) acc2[i][j] = 0ull;

    for (int c0 = 0; c0 < CFULL; c0 += 32) {
        __syncthreads();
#pragma unroll
        for (int i = 0; i < 8; i++) {           // 64o x 32k W tile
            int idx = tid + i * 256;
            int k = idx & 31, o = idx >> 5;
            Ws[k * 68 + o] = W[o * CFULL + c0 + k];
        }
#pragma unroll
        for (int i = 0; i < 4; i++) {           // 32k x 128 X tile, float4
            int ch = tid + i * 256;
            int k = ch >> 5, j4 = ch & 31;
            *(float4*)&Xs[k * 128 + j4 * 4] =
                *(const float4*)&X[(size_t)(c0 + k) * HW + hw0 + j4 * 4];
        }
        __syncthreads();
#pragma unroll
        for (int k = 0; k < 32; k++) {
            float4 a4 = *(const float4*)&Ws[k * 68 + ty * 4];
            u64 ad[4] = {dup2(a4.x), dup2(a4.y), dup2(a4.z), dup2(a4.w)};
            ulonglong2 b0 = *(const ulonglong2*)&Xs[k * 128 + tx * 8];
            ulonglong2 b1 = *(const ulonglong2*)&Xs[k * 128 + tx * 8 + 4];
            u64 bb[4] = {b0.x, b0.y, b1.x, b1.y};
#pragma unroll
            for (int i = 0; i < 4; i++)
#pragma unroll
                for (int j = 0; j < 4; j++) fma2(acc2[i][j], ad[i], bb[j]);
        }
    }

    // unpack + bias
    float v[4][8];
#pragma unroll
    for (int i = 0; i < 4; i++) {
        float bo = bias[ty * 4 + i];
#pragma unroll
        for (int j = 0; j < 4; j++) {
            float2 t = unpk(acc2[i][j]);
            v[i][2 * j]     = t.x + bo;
            v[i][2 * j + 1] = t.y + bo;
        }
    }

    float* out = g_proj + (size_t)(p * 4 + b) * C4 * HW;
    if (p != 3) {
        // natural [o][hw]
#pragma unroll
        for (int i = 0; i < 4; i++) {
            int o = ty * 4 + i;
            *(float4*)&out[(size_t)o * HW + hw0 + tx * 8] =
                make_float4(v[i][0], v[i][1], v[i][2], v[i][3]);
            *(float4*)&out[(size_t)o * HW + hw0 + tx * 8 + 4] =
                make_float4(v[i][4], v[i][5], v[i][6], v[i][7]);
        }
    } else {
        // transposed [hw][o] via smem staging
        __syncthreads();   // everyone done reading Ws/Xs before aliasing Ts
#pragma unroll
        for (int j = 0; j < 8; j++) {
            int hw = tx * 8 + j;
            *(u64*)&Ts[hw * 66 + ty * 4]     = pack2(v[0][j], v[1][j]);
            *(u64*)&Ts[hw * 66 + ty * 4 + 2] = pack2(v[2][j], v[3][j]);
        }
        __syncthreads();
#pragma unroll
        for (int i2 = 0; i2 < 16; i2++) {
            int ch = tid + i2 * 256;        // float2 chunks: 128 rows x 32
            int r = ch >> 5, c2 = ch & 31;
            *(float2*)&out[(size_t)(hw0 + r) * C4 + 2 * c2] =
                *(const float2*)&Ts[r * 66 + 2 * c2];
        }
    }
}

// ---------------------------------------------------------------------------
// Kernel 2: flash attention, FFMA2 OUTER-product form.
// Bq=64, Bk=128, 256 threads (16tx x 16ty). Per thread: 4 q, 8 k (GEMM1),
// 4 q x 4 c (GEMM2, c-packed pairs).
// smem: Qs[d][q] 64x64, Ks[d][k] 64x128, Vt[k][c] 128x64, Ps[k][q] 128x64
// (Ps column XOR-swizzled by key=(k>>3)&7 to break store bank conflicts).
// All hot-loop LDS are uniform-row -> conflict-free.
// ---------------------------------------------------------------------------
__global__ __launch_bounds__(256, 2) void attn_kernel()
{
    extern __shared__ __align__(16) float sm[];
    float* Qs = sm;                          // 64*64
    float* Ks = sm + 4096;                   // 64*128
    float* Vt = sm + 4096 + 8192;            // 128*64
    float* Ps = sm + 4096 + 8192 + 8192;     // 128*64

    int tid = threadIdx.x;
    int tx = tid & 15, ty = tid >> 4;
    int b = blockIdx.z, a = blockIdx.y;
    int q0 = blockIdx.x * 64;

    const float* qb = g_proj + (size_t)(0 * 4 + b) * C4 * HW;        // [64][HW]
    const float* kb = g_proj + (size_t)((1 + a) * 4 + b) * C4 * HW;  // [64][HW]
    const float* vT = g_proj + (size_t)(3 * 4 + b) * C4 * HW;        // [HW][64]

    // load Q tile [d][q], coalesced
#pragma unroll
    for (int i = 0; i < 4; i++) {
        int ch = tid + i * 256;              // 1024 float4 chunks
        int d = ch >> 4, q4 = ch & 15;
        *(float4*)&Qs[d * 64 + q4 * 4] =
            *(const float4*)&qb[(size_t)d * HW + q0 + q4 * 4];
    }

    u64 acc2[4][2];
    float m[4], l[4];
#pragma unroll
    for (int i = 0; i < 4; i++) {
        m[i] = -1e30f; l[i] = 0.f;
        acc2[i][0] = 0ull; acc2[i][1] = 0ull;
    }

    for (int kt = 0; kt < 32; kt++) {
        int k0 = kt * 128;
        __syncthreads();   // prev GEMM2 done with Ps/Vt
        // fill Ks 64x128 and Vt 128x64 (2048 float4 each)
#pragma unroll
        for (int i = 0; i < 8; i++) {
            int ch = tid + i * 256;
            int d = ch >> 5, p4 = ch & 31;
            *(float4*)&Ks[d * 128 + p4 * 4] =
                *(const float4*)&kb[(size_t)d * HW + k0 + p4 * 4];
            int kr = ch >> 4, c4 = ch & 15;
            *(float4*)&Vt[kr * 64 + c4 * 4] =
                *(const float4*)&vT[(size_t)(k0 + kr) * 64 + c4 * 4];
        }
        __syncthreads();

        // GEMM1: S[q][k] = sum_d Q[d][q] * K[d][k], k-pair packed
        u64 s2[4][4];
#pragma unroll
        for (int i = 0; i < 4; i++)
#pragma unroll
            for (int j = 0; j < 4; j++) s2[i][j] = 0ull;
#pragma unroll 8
        for (int d = 0; d < 64; d++) {
            float4 a4 = *(const float4*)&Qs[d * 64 + ty * 4];
            u64 ad[4] = {dup2(a4.x), dup2(a4.y), dup2(a4.z), dup2(a4.w)};
            ulonglong2 b0 = *(const ulonglong2*)&Ks[d * 128 + tx * 8];
            ulonglong2 b1 = *(const ulonglong2*)&Ks[d * 128 + tx * 8 + 4];
            u64 bb[4] = {b0.x, b0.y, b1.x, b1.y};
#pragma unroll
            for (int i = 0; i < 4; i++)
#pragma unroll
                for (int j = 0; j < 4; j++) fma2(s2[i][j], ad[i], bb[j]);
        }

        // online softmax over 128-key tile (reduce across 16 tx lanes)
#pragma unroll
        for (int i = 0; i < 4; i++) {
            float e[8];
            float rm = -1e30f;
#pragma unroll
            for (int j = 0; j < 4; j++) {
                float2 t = unpk(s2[i][j]);
                e[2 * j] = t.x; e[2 * j + 1] = t.y;
                rm = fmaxf(rm, fmaxf(t.x, t.y));
            }
            rm = fmaxf(rm, __shfl_xor_sync(0xffffffffu, rm, 1));
            rm = fmaxf(rm, __shfl_xor_sync(0xffffffffu, rm, 2));
            rm = fmaxf(rm, __shfl_xor_sync(0xffffffffu, rm, 4));
            rm = fmaxf(rm, __shfl_xor_sync(0xffffffffu, rm, 8));
            float mn = fmaxf(m[i], rm);
            float sc = __expf(m[i] - mn);
            m[i] = mn;
            float ps = 0.f;
#pragma unroll
            for (int j = 0; j < 8; j++) { e[j] = __expf(e[j] - mn); ps += e[j]; }
            ps += __shfl_xor_sync(0xffffffffu, ps, 1);
            ps += __shfl_xor_sync(0xffffffffu, ps, 2);
            ps += __shfl_xor_sync(0xffffffffu, ps, 4);
            ps += __shfl_xor_sync(0xffffffffu, ps, 8);
            l[i] = l[i] * sc + ps;
            u64 sc2 = dup2(sc);
            mul2(acc2[i][0], sc2);
            mul2(acc2[i][1], sc2);
            // store P[k][q] with XOR column swizzle, key = (k>>3)&7 = tx&7
            int colx = (ty * 4 + i) ^ ((tx & 7) << 2);
#pragma unroll
            for (int j = 0; j < 8; j++)
                Ps[(tx * 8 + j) * 64 + colx] = e[j];
        }
        __syncthreads();

        // GEMM2: O[q][c] += sum_k P[k][q] * V[k][c], c-pair packed
#pragma unroll 2
        for (int g = 0; g < 16; g++) {
            int key = (g & 7) << 2;
#pragma unroll
            for (int r = 0; r < 8; r++) {
                int kk = g * 8 + r;
                ulonglong2 bv = *(const ulonglong2*)&Vt[kk * 64 + tx * 4];
#pragma unroll
                for (int i = 0; i < 4; i++) {
                    u64 ad = dup2(Ps[kk * 64 + ((ty * 4 + i) ^ key)]);
                    fma2(acc2[i][0], ad, bv.x);
                    fma2(acc2[i][1], ad, bv.y);
                }
            }
        }
    }

    // epilogue: unpack (no horizontal sums needed), normalize, write fused[c][q]
    float* fo = g_fused + (size_t)b * 128 * HW + (size_t)a * 64 * HW;
    float val[4][4];
#pragma unroll
    for (int i = 0; i < 4; i++) {
        float inv = 1.f / l[i];
        float2 t0 = unpk(acc2[i][0]);
        float2 t1 = unpk(acc2[i][1]);
        val[i][0] = t0.x * inv; val[i][1] = t0.y * inv;
        val[i][2] = t1.x * inv; val[i][3] = t1.y * inv;
    }
#pragma unroll
    for (int cj = 0; cj < 4; cj++) {
        *(float4*)&fo[(size_t)(tx * 4 + cj) * HW + q0 + ty * 4] =
            make_float4(val[0][cj], val[1][cj], val[2][cj], val[3][cj]);
    }
}

// ---------------------------------------------------------------------------
// Kernel 3: fire conv (128->256) + BN + residual + ReLU, FFMA2 outer product.
// ---------------------------------------------------------------------------
__global__ __launch_bounds__(256) void fire_kernel(
    const float* __restrict__ Wfire, const float* __restrict__ bfire,
    const float* __restrict__ gamma, const float* __restrict__ beta,
    const float* __restrict__ mean,  const float* __restrict__ var,
    const float* __restrict__ cur, float* __restrict__ out)
{
    __shared__ __align__(16) float sbuf[32 * 68 + 32 * 128];
    float* Ws = sbuf;
    float* Xs = sbuf + 32 * 68;

    int b = blockIdx.z;
    int o0 = blockIdx.y * 64;
    int hw0 = blockIdx.x * 128;
    const float* X = g_fused + (size_t)b * 128 * HW;
    int tid = threadIdx.x, tx = tid & 15, ty = tid >> 4;

    u64 acc2[4][4];
#pragma unroll
    for (int i = 0; i < 4; i++)
#pragma unroll
        for (int j = 0; j < 4; j++) acc2[i][j] = 0ull;

    for (int c0 = 0; c0 < 128; c0 += 32) {
        __syncthreads();
#pragma unroll
        for (int i = 0; i < 8; i++) {
            int idx = tid + i * 256;
            int k = idx & 31, o = idx >> 5;
            Ws[k * 68 + o] = Wfire[(size_t)(o0 + o) * 128 + c0 + k];
        }
#pragma unroll
        for (int i = 0; i < 4; i++) {
            int ch = tid + i * 256;
            int k = ch >> 5, j4 = ch & 31;
            *(float4*)&Xs[k * 128 + j4 * 4] =
                *(const float4*)&X[(size_t)(c0 + k) * HW + hw0 + j4 * 4];
        }
        __syncthreads();
#pragma unroll
        for (int k = 0; k < 32; k++) {
            float4 a4 = *(const float4*)&Ws[k * 68 + ty * 4];
            u64 ad[4] = {dup2(a4.x), dup2(a4.y), dup2(a4.z), dup2(a4.w)};
            ulonglong2 b0 = *(const ulonglong2*)&Xs[k * 128 + tx * 8];
            ulonglong2 b1 = *(const ulonglong2*)&Xs[k * 128 + tx * 8 + 4];
            u64 bb[4] = {b0.x, b0.y, b1.x, b1.y};
#pragma unroll
            for (int i = 0; i < 4; i++)
#pragma unroll
                for (int j = 0; j < 4; j++) fma2(acc2[i][j], ad[i], bb[j]);
        }
    }

#pragma unroll
    for (int i = 0; i < 4; i++) {
        int o = o0 + ty * 4 + i;
        float inv = gamma[o] * rsqrtf(var[o] + 1e-5f);
        float sh  = beta[o] - mean[o] * inv;
        float bo  = bfire[o];
        float v[8];
#pragma unroll
        for (int j = 0; j < 4; j++) {
            float2 t = unpk(acc2[i][j]);
            v[2 * j]     = t.x;
            v[2 * j + 1] = t.y;
        }
#pragma unroll
        for (int j = 0; j < 8; j++) {
            size_t idx = ((size_t)b * CFULL + o) * HW + hw0 + tx * 8 + j;
            float fired = (v[j] + bo) * inv + sh;
            out[idx] = fmaxf(cur[idx] + fired, 0.f);
        }
    }
}

// ---------------------------------------------------------------------------
extern "C" void kernel_launch(void* const* d_in, const int* in_sizes, int n_in,
                              void* d_out, int out_size)
{
    const float* last  = (const float*)d_in[0];
    const float* cur   = (const float*)d_in[1];
    const float* fut   = (const float*)d_in[2];
    const float* Wqk   = (const float*)d_in[3];
    const float* bqk   = (const float*)d_in[4];
    const float* Wkl   = (const float*)d_in[5];
    const float* bkl   = (const float*)d_in[6];
    const float* Wkf   = (const float*)d_in[7];
    const float* bkf   = (const float*)d_in[8];
    const float* Wv    = (const float*)d_in[9];
    const float* bv    = (const float*)d_in[10];
    const float* Wfire = (const float*)d_in[11];
    const float* bfire = (const float*)d_in[12];
    const float* gamma = (const float*)d_in[13];
    const float* beta  = (const float*)d_in[14];
    const float* mean  = (const float*)d_in[15];
    const float* var   = (const float*)d_in[16];
    float* out = (float*)d_out;

    dim3 gA(HW / 128, 4, BATCH);
    proj_kernel<<<gA, 256>>>(last, cur, fut, Wqk, bqk, Wkl, bkl, Wkf, bkf, Wv, bv);

    size_t smB = (size_t)(4096 + 8192 + 8192 + 8192) * sizeof(float);   // 114688 B
    cudaFuncSetAttribute(attn_kernel, cudaFuncAttributeMaxDynamicSharedMemorySize, (int)smB);
    dim3 gB(HW / 64, 2, BATCH);
    attn_kernel<<<gB, 256, smB>>>();

    dim3 gC(HW / 128, CFULL / 64, BATCH);
    fire_kernel<<<gC, 256>>>(Wfire, bfire, gamma, beta, mean, var, cur, out);
}

// round 15
// speedup vs baseline: 1.9216x; 1.1047x over previous
#include <cuda_runtime.h>
#include <math.h>

#define HW    4096
#define CFULL 256
#define C4    64
#define BATCH 4

typedef unsigned long long u64;

// Scratch: projections. q(p=0), kl(p=1), kf(p=2) stored natural [64][HW];
// v (p=3) stored TRANSPOSED [HW][64]. Each slot is 64*4096 floats.
__device__ float g_proj[(size_t)16 * C4 * HW];          // 16 MB
__device__ float g_fused[(size_t)BATCH * 128 * HW];     // 8 MB

// ---------------- packed f32x2 helpers (sm_103a FFMA2 path) ----------------
__device__ __forceinline__ u64 pack2(float x, float y) {
    u64 r; asm("mov.b64 %0, {%1, %2};" : "=l"(r) : "f"(x), "f"(y)); return r;
}
__device__ __forceinline__ u64 dup2(float x) {
    u64 r; asm("mov.b64 %0, {%1, %1};" : "=l"(r) : "f"(x)); return r;
}
__device__ __forceinline__ float2 unpk(u64 v) {
    float2 f; asm("mov.b64 {%0, %1}, %2;" : "=f"(f.x), "=f"(f.y) : "l"(v)); return f;
}
__device__ __forceinline__ void fma2(u64& d, u64 a, u64 b) {
    asm("fma.rn.f32x2 %0, %1, %2, %0;" : "+l"(d) : "l"(a), "l"(b));
}
__device__ __forceinline__ void mul2(u64& d, u64 a) {
    asm("mul.rn.f32x2 %0, %0, %1;" : "+l"(d) : "l"(a));
}

// ---------------------------------------------------------------------------
// Kernel 1: fused 1x1-conv projections with FFMA2 (outer product).
// p: 0=q(cur,Wqk) 1=kl(last,Wkl) 2=kf(fut,Wkf) 3=v(cur,Wv)
// p<3 -> natural [o][hw]; p==3 -> transposed [hw][o].
// ---------------------------------------------------------------------------
__global__ __launch_bounds__(256) void proj_kernel(
    const float* __restrict__ last, const float* __restrict__ cur, const float* __restrict__ fut,
    const float* __restrict__ Wqk, const float* __restrict__ bqk,
    const float* __restrict__ Wkl, const float* __restrict__ bkl,
    const float* __restrict__ Wkf, const float* __restrict__ bkf,
    const float* __restrict__ Wv,  const float* __restrict__ bv)
{
    __shared__ __align__(16) float sbuf[128 * 66];   // reused as Ts for transpose
    float* Ws = sbuf;                 // 32 x 68 (pad)
    float* Xs = sbuf + 32 * 68;       // 32 x 128
    float* Ts = sbuf;                 // 128 x 66 transpose staging

    int p = blockIdx.y, b = blockIdx.z;
    const float* X; const float* W; const float* bias;
    if (p == 0)      { X = cur;  W = Wqk; bias = bqk; }
    else if (p == 1) { X = last; W = Wkl; bias = bkl; }
    else if (p == 2) { X = fut;  W = Wkf; bias = bkf; }
    else             { X = cur;  W = Wv;  bias = bv;  }
    X += (size_t)b * CFULL * HW;

    int hw0 = blockIdx.x * 128;
    int tid = threadIdx.x;
    int tx = tid & 15, ty = tid >> 4;

    u64 acc2[4][4];
#pragma unroll
    for (int i = 0; i < 4; i++)
#pragma unroll
        for (int j = 0; j < 4; j++) acc2[i][j] = 0ull;

    for (int c0 = 0; c0 < CFULL; c0 += 32) {
        __syncthreads();
#pragma unroll
        for (int i = 0; i < 8; i++) {           // 64o x 32k W tile
            int idx = tid + i * 256;
            int k = idx & 31, o = idx >> 5;
            Ws[k * 68 + o] = W[o * CFULL + c0 + k];
        }
#pragma unroll
        for (int i = 0; i < 4; i++) {           // 32k x 128 X tile, float4
            int ch = tid + i * 256;
            int k = ch >> 5, j4 = ch & 31;
            *(float4*)&Xs[k * 128 + j4 * 4] =
                *(const float4*)&X[(size_t)(c0 + k) * HW + hw0 + j4 * 4];
        }
        __syncthreads();
#pragma unroll
        for (int k = 0; k < 32; k++) {
            float4 a4 = *(const float4*)&Ws[k * 68 + ty * 4];
            u64 ad[4] = {dup2(a4.x), dup2(a4.y), dup2(a4.z), dup2(a4.w)};
            ulonglong2 b0 = *(const ulonglong2*)&Xs[k * 128 + tx * 8];
            ulonglong2 b1 = *(const ulonglong2*)&Xs[k * 128 + tx * 8 + 4];
            u64 bb[4] = {b0.x, b0.y, b1.x, b1.y};
#pragma unroll
            for (int i = 0; i < 4; i++)
#pragma unroll
                for (int j = 0; j < 4; j++) fma2(acc2[i][j], ad[i], bb[j]);
        }
    }

    // unpack + bias
    float v[4][8];
#pragma unroll
    for (int i = 0; i < 4; i++) {
        float bo = bias[ty * 4 + i];
#pragma unroll
        for (int j = 0; j < 4; j++) {
            float2 t = unpk(acc2[i][j]);
            v[i][2 * j]     = t.x + bo;
            v[i][2 * j + 1] = t.y + bo;
        }
    }

    float* out = g_proj + (size_t)(p * 4 + b) * C4 * HW;
    if (p != 3) {
        // natural [o][hw]
#pragma unroll
        for (int i = 0; i < 4; i++) {
            int o = ty * 4 + i;
            *(float4*)&out[(size_t)o * HW + hw0 + tx * 8] =
                make_float4(v[i][0], v[i][1], v[i][2], v[i][3]);
            *(float4*)&out[(size_t)o * HW + hw0 + tx * 8 + 4] =
                make_float4(v[i][4], v[i][5], v[i][6], v[i][7]);
        }
    } else {
        // transposed [hw][o] via smem staging
        __syncthreads();   // everyone done reading Ws/Xs before aliasing Ts
#pragma unroll
        for (int j = 0; j < 8; j++) {
            int hw = tx * 8 + j;
            *(u64*)&Ts[hw * 66 + ty * 4]     = pack2(v[0][j], v[1][j]);
            *(u64*)&Ts[hw * 66 + ty * 4 + 2] = pack2(v[2][j], v[3][j]);
        }
        __syncthreads();
#pragma unroll
        for (int i2 = 0; i2 < 16; i2++) {
            int ch = tid + i2 * 256;        // float2 chunks: 128 rows x 32
            int r = ch >> 5, c2 = ch & 31;
            *(float2*)&out[(size_t)(hw0 + r) * C4 + 2 * c2] =
                *(const float2*)&Ts[r * 66 + 2 * c2];
        }
    }
}

// ---------------------------------------------------------------------------
// Kernel 2: flash attention, FFMA2 outer-product form.
// Bq=64, Bk=128, 256 threads (16tx x 16ty). Per thread: 4q x 8k (GEMM1),
// 4q x 4c (GEMM2).
// smem (80 KB -> 2 CTAs/SM): Qs[d][q] 64x64, Ks[d][k] 64x128 (ALIASED as
// Ps[k][q] 128x64 after GEMM1), Vt[k][c] 128x64.
// Ps columns XOR-swizzled by key=(k>>3)&7 (bits 2..4) so the per-thread 4 q
// values stay contiguous -> float4 loads in GEMM2, 2-way max store conflicts.
// ---------------------------------------------------------------------------
__global__ __launch_bounds__(256, 2) void attn_kernel()
{
    extern __shared__ __align__(16) float sm[];
    float* Qs = sm;                          // 64*64
    float* Ks = sm + 4096;                   // 64*128
    float* Vt = sm + 4096 + 8192;            // 128*64
    float* Ps = Ks;                          // alias: live only after GEMM1

    int tid = threadIdx.x;
    int tx = tid & 15, ty = tid >> 4;
    int b = blockIdx.z, a = blockIdx.y;
    int q0 = blockIdx.x * 64;

    const float* qb = g_proj + (size_t)(0 * 4 + b) * C4 * HW;        // [64][HW]
    const float* kb = g_proj + (size_t)((1 + a) * 4 + b) * C4 * HW;  // [64][HW]
    const float* vT = g_proj + (size_t)(3 * 4 + b) * C4 * HW;        // [HW][64]

    // load Q tile [d][q], coalesced
#pragma unroll
    for (int i = 0; i < 4; i++) {
        int ch = tid + i * 256;              // 1024 float4 chunks
        int d = ch >> 4, q4 = ch & 15;
        *(float4*)&Qs[d * 64 + q4 * 4] =
            *(const float4*)&qb[(size_t)d * HW + q0 + q4 * 4];
    }

    u64 acc2[4][2];
    float m[4], l[4];
#pragma unroll
    for (int i = 0; i < 4; i++) {
        m[i] = -1e30f; l[i] = 0.f;
        acc2[i][0] = 0ull; acc2[i][1] = 0ull;
    }

    for (int kt = 0; kt < 32; kt++) {
        int k0 = kt * 128;
        __syncthreads();   // prev GEMM2 done with Ps(=Ks) and Vt
        // fill Ks 64x128 and Vt 128x64 (2048 float4 each)
#pragma unroll
        for (int i = 0; i < 8; i++) {
            int ch = tid + i * 256;
            int d = ch >> 5, p4 = ch & 31;
            *(float4*)&Ks[d * 128 + p4 * 4] =
                *(const float4*)&kb[(size_t)d * HW + k0 + p4 * 4];
            int kr = ch >> 4, c4 = ch & 15;
            *(float4*)&Vt[kr * 64 + c4 * 4] =
                *(const float4*)&vT[(size_t)(k0 + kr) * 64 + c4 * 4];
        }
        __syncthreads();

        // GEMM1: S[q][k] = sum_d Q[d][q] * K[d][k], k-pair packed
        u64 s2[4][4];
#pragma unroll
        for (int i = 0; i < 4; i++)
#pragma unroll
            for (int j = 0; j < 4; j++) s2[i][j] = 0ull;
#pragma unroll 8
        for (int d = 0; d < 64; d++) {
            float4 a4 = *(const float4*)&Qs[d * 64 + ty * 4];
            u64 ad[4] = {dup2(a4.x), dup2(a4.y), dup2(a4.z), dup2(a4.w)};
            ulonglong2 b0 = *(const ulonglong2*)&Ks[d * 128 + tx * 8];
            ulonglong2 b1 = *(const ulonglong2*)&Ks[d * 128 + tx * 8 + 4];
            u64 bb[4] = {b0.x, b0.y, b1.x, b1.y};
#pragma unroll
            for (int i = 0; i < 4; i++)
#pragma unroll
                for (int j = 0; j < 4; j++) fma2(s2[i][j], ad[i], bb[j]);
        }
        __syncthreads();   // all warps done reading Ks before Ps overwrites it

        // online softmax over 128-key tile (reduce across 16 tx lanes)
#pragma unroll
        for (int i = 0; i < 4; i++) {
            float e[8];
            float rm = -1e30f;
#pragma unroll
            for (int j = 0; j < 4; j++) {
                float2 t = unpk(s2[i][j]);
                e[2 * j] = t.x; e[2 * j + 1] = t.y;
                rm = fmaxf(rm, fmaxf(t.x, t.y));
            }
            rm = fmaxf(rm, __shfl_xor_sync(0xffffffffu, rm, 1));
            rm = fmaxf(rm, __shfl_xor_sync(0xffffffffu, rm, 2));
            rm = fmaxf(rm, __shfl_xor_sync(0xffffffffu, rm, 4));
            rm = fmaxf(rm, __shfl_xor_sync(0xffffffffu, rm, 8));
            float mn = fmaxf(m[i], rm);
            float sc = __expf(m[i] - mn);
            m[i] = mn;
            float ps = 0.f;
#pragma unroll
            for (int j = 0; j < 8; j++) { e[j] = __expf(e[j] - mn); ps += e[j]; }
            ps += __shfl_xor_sync(0xffffffffu, ps, 1);
            ps += __shfl_xor_sync(0xffffffffu, ps, 2);
            ps += __shfl_xor_sync(0xffffffffu, ps, 4);
            ps += __shfl_xor_sync(0xffffffffu, ps, 8);
            l[i] = l[i] * sc + ps;
            u64 sc2 = dup2(sc);
            mul2(acc2[i][0], sc2);
            mul2(acc2[i][1], sc2);
            // store P[k][q] with XOR column swizzle, key = (k>>3)&7 = tx&7
            int colx = (ty * 4 + i) ^ ((tx & 7) << 2);
#pragma unroll
            for (int j = 0; j < 8; j++)
                Ps[(tx * 8 + j) * 64 + colx] = e[j];
        }
        __syncthreads();

        // GEMM2: O[q][c] += sum_k P[k][q] * V[k][c], c-pair packed.
        // Swizzle key bits (2..4) don't touch bits 0..1, so the 4 q values of
        // this thread are contiguous: one float4 per kk.
#pragma unroll 2
        for (int g = 0; g < 16; g++) {
            int col4 = (ty * 4) ^ ((g & 7) << 2);
#pragma unroll
            for (int r = 0; r < 8; r++) {
                int kk = g * 8 + r;
                ulonglong2 bv = *(const ulonglong2*)&Vt[kk * 64 + tx * 4];
                float4 p4 = *(const float4*)&Ps[kk * 64 + col4];
                u64 a0 = dup2(p4.x), a1 = dup2(p4.y), a2 = dup2(p4.z), a3 = dup2(p4.w);
                fma2(acc2[0][0], a0, bv.x); fma2(acc2[0][1], a0, bv.y);
                fma2(acc2[1][0], a1, bv.x); fma2(acc2[1][1], a1, bv.y);
                fma2(acc2[2][0], a2, bv.x); fma2(acc2[2][1], a2, bv.y);
                fma2(acc2[3][0], a3, bv.x); fma2(acc2[3][1], a3, bv.y);
            }
        }
    }

    // epilogue: unpack, normalize, write fused[c][q]
    float* fo = g_fused + (size_t)b * 128 * HW + (size_t)a * 64 * HW;
    float val[4][4];
#pragma unroll
    for (int i = 0; i < 4; i++) {
        float inv = 1.f / l[i];
        float2 t0 = unpk(acc2[i][0]);
        float2 t1 = unpk(acc2[i][1]);
        val[i][0] = t0.x * inv; val[i][1] = t0.y * inv;
        val[i][2] = t1.x * inv; val[i][3] = t1.y * inv;
    }
#pragma unroll
    for (int cj = 0; cj < 4; cj++) {
        *(float4*)&fo[(size_t)(tx * 4 + cj) * HW + q0 + ty * 4] =
            make_float4(val[0][cj], val[1][cj], val[2][cj], val[3][cj]);
    }
}

// ---------------------------------------------------------------------------
// Kernel 3: fire conv (128->256) + BN + residual + ReLU, FFMA2 outer product.
// ---------------------------------------------------------------------------
__global__ __launch_bounds__(256) void fire_kernel(
    const float* __restrict__ Wfire, const float* __restrict__ bfire,
    const float* __restrict__ gamma, const float* __restrict__ beta,
    const float* __restrict__ mean,  const float* __restrict__ var,
    const float* __restrict__ cur, float* __restrict__ out)
{
    __shared__ __align__(16) float sbuf[32 * 68 + 32 * 128];
    float* Ws = sbuf;
    float* Xs = sbuf + 32 * 68;

    int b = blockIdx.z;
    int o0 = blockIdx.y * 64;
    int hw0 = blockIdx.x * 128;
    const float* X = g_fused + (size_t)b * 128 * HW;
    int tid = threadIdx.x, tx = tid & 15, ty = tid >> 4;

    u64 acc2[4][4];
#pragma unroll
    for (int i = 0; i < 4; i++)
#pragma unroll
        for (int j = 0; j < 4; j++) acc2[i][j] = 0ull;

    for (int c0 = 0; c0 < 128; c0 += 32) {
        __syncthreads();
#pragma unroll
        for (int i = 0; i < 8; i++) {
            int idx = tid + i * 256;
            int k = idx & 31, o = idx >> 5;
            Ws[k * 68 + o] = Wfire[(size_t)(o0 + o) * 128 + c0 + k];
        }
#pragma unroll
        for (int i = 0; i < 4; i++) {
            int ch = tid + i * 256;
            int k = ch >> 5, j4 = ch & 31;
            *(float4*)&Xs[k * 128 + j4 * 4] =
                *(const float4*)&X[(size_t)(c0 + k) * HW + hw0 + j4 * 4];
        }
        __syncthreads();
#pragma unroll
        for (int k = 0; k < 32; k++) {
            float4 a4 = *(const float4*)&Ws[k * 68 + ty * 4];
            u64 ad[4] = {dup2(a4.x), dup2(a4.y), dup2(a4.z), dup2(a4.w)};
            ulonglong2 b0 = *(const ulonglong2*)&Xs[k * 128 + tx * 8];
            ulonglong2 b1 = *(const ulonglong2*)&Xs[k * 128 + tx * 8 + 4];
            u64 bb[4] = {b0.x, b0.y, b1.x, b1.y};
#pragma unroll
            for (int i = 0; i < 4; i++)
#pragma unroll
                for (int j = 0; j < 4; j++) fma2(acc2[i][j], ad[i], bb[j]);
        }
    }

#pragma unroll
    for (int i = 0; i < 4; i++) {
        int o = o0 + ty * 4 + i;
        float inv = gamma[o] * rsqrtf(var[o] + 1e-5f);
        float sh  = beta[o] - mean[o] * inv;
        float bo  = bfire[o];
        float v[8];
#pragma unroll
        for (int j = 0; j < 4; j++) {
            float2 t = unpk(acc2[i][j]);
            v[2 * j]     = t.x;
            v[2 * j + 1] = t.y;
        }
#pragma unroll
        for (int j = 0; j < 8; j++) {
            size_t idx = ((size_t)b * CFULL + o) * HW + hw0 + tx * 8 + j;
            float fired = (v[j] + bo) * inv + sh;
            out[idx] = fmaxf(cur[idx] + fired, 0.f);
        }
    }
}

// ---------------------------------------------------------------------------
extern "C" void kernel_launch(void* const* d_in, const int* in_sizes, int n_in,
                              void* d_out, int out_size)
{
    const float* last  = (const float*)d_in[0];
    const float* cur   = (const float*)d_in[1];
    const float* fut   = (const float*)d_in[2];
    const float* Wqk   = (const float*)d_in[3];
    const float* bqk   = (const float*)d_in[4];
    const float* Wkl   = (const float*)d_in[5];
    const float* bkl   = (const float*)d_in[6];
    const float* Wkf   = (const float*)d_in[7];
    const float* bkf   = (const float*)d_in[8];
    const float* Wv    = (const float*)d_in[9];
    const float* bv    = (const float*)d_in[10];
    const float* Wfire = (const float*)d_in[11];
    const float* bfire = (const float*)d_in[12];
    const float* gamma = (const float*)d_in[13];
    const float* beta  = (const float*)d_in[14];
    const float* mean  = (const float*)d_in[15];
    const float* var   = (const float*)d_in[16];
    float* out = (float*)d_out;

    dim3 gA(HW / 128, 4, BATCH);
    proj_kernel<<<gA, 256>>>(last, cur, fut, Wqk, bqk, Wkl, bkl, Wkf, bkf, Wv, bv);

    size_t smB = (size_t)(4096 + 8192 + 8192) * sizeof(float);   // 81920 B -> 2 CTAs/SM
    cudaFuncSetAttribute(attn_kernel, cudaFuncAttributeMaxDynamicSharedMemorySize, (int)smB);
    dim3 gB(HW / 64, 2, BATCH);
    attn_kernel<<<gB, 256, smB>>>();

    dim3 gC(HW / 128, CFULL / 64, BATCH);
    fire_kernel<<<gC, 256>>>(Wfire, bfire, gamma, beta, mean, var, cur, out);
}